// round 1
// baseline (speedup 1.0000x reference)
#include <cuda_runtime.h>
#include <cstdint>

typedef unsigned long long u64;

// ---- packed f32x2 helpers (B300: FFMA2 doubles fp32 rate, PTX-only) ----
__device__ __forceinline__ u64 ffma2(u64 a, u64 b, u64 c) {
    u64 d;
    asm("fma.rn.f32x2 %0, %1, %2, %3;" : "=l"(d) : "l"(a), "l"(b), "l"(c));
    return d;
}
__device__ __forceinline__ u64 pk(float x, float y) {
    u64 r; asm("mov.b64 %0, {%1, %2};" : "=l"(r) : "f"(x), "f"(y)); return r;
}
__device__ __forceinline__ float2 unpk(u64 v) {
    float2 r;
    asm("mov.b64 {%0, %1}, %2;" : "=f"(r.x), "=f"(r.y) : "l"(v));
    return r;
}

#define KD 25088      // D = 512*7*7
#define KH 4096       // hidden
#define NROI 2048     // B*N
#define NOUT 25       // 21 cls + 4 reg
#define NCLS_ 21
#define HSPLIT 16     // split of KH across blocks (parallelism for k1)
#define HPER (KH / HSPLIT)   // 256
#define HCHUNK 128           // shared P tile
#define DCHUNK 256           // k2 shared M tile (floats)

// scratch (static device arrays: no allocations allowed)
__device__ __align__(16) float g_part[(size_t)HSPLIT * NOUT * KD]; // 40.1 MB
__device__ __align__(16) float g_M[NOUT * KD];                     // 2.5 MB
__device__ float g_biasf[NOUT];
__device__ float g_score[NROI];
__device__ __align__(16) float g_boxes[NROI * 4];

// ---------------- fused bias: bias_f[c] = sum_h b1[h]*P[c,h] + (bc|br)[c] ----------------
__global__ void k_bias(const float* __restrict__ b1, const float* __restrict__ Wc,
                       const float* __restrict__ bc, const float* __restrict__ Wr,
                       const float* __restrict__ br) {
    int c = blockIdx.x;
    int tid = threadIdx.x;
    const float* p = (c < NCLS_) ? (Wc + (size_t)c * KH) : (Wr + (size_t)(c - NCLS_) * KH);
    float s = 0.f;
    for (int h = tid; h < KH; h += 256) s += b1[h] * p[h];
    __shared__ float red[256];
    red[tid] = s;
    __syncthreads();
    for (int o = 128; o > 0; o >>= 1) {
        if (tid < o) red[tid] += red[tid + o];
        __syncthreads();
    }
    if (tid == 0) g_biasf[c] = red[0] + ((c < NCLS_) ? bc[c] : br[c - NCLS_]);
}

// ---------------- k1: partial M[c,d] = sum_{h in chunk} P[c,h] * W1[h,d] ----------------
// grid (49, HSPLIT), 256 threads. Each thread owns 2 consecutive d (one f32x2 lane-pair).
// P chunk is stored PRE-DUPLICATED in shared as (v,v) so LDS.64 broadcast feeds FFMA2
// with no per-step pack instruction.
__global__ __launch_bounds__(256) void k1_partial(const float* __restrict__ W1,
                                                  const float* __restrict__ Wc,
                                                  const float* __restrict__ Wr) {
    __shared__ u64 sP[NOUT][HCHUNK];
    int tid = threadIdx.x;
    int d = blockIdx.x * 512 + tid * 2;
    int hbase = blockIdx.y * HPER;

    u64 acc[NOUT];
#pragma unroll
    for (int c = 0; c < NOUT; c++) acc[c] = 0ull;

    for (int ch = 0; ch < HPER / HCHUNK; ch++) {
        int h0 = hbase + ch * HCHUNK;
        __syncthreads();
        for (int idx = tid; idx < NOUT * HCHUNK; idx += 256) {
            int c = idx / HCHUNK, j = idx % HCHUNK;
            float v = (c < NCLS_) ? Wc[(size_t)c * KH + h0 + j]
                                  : Wr[(size_t)(c - NCLS_) * KH + h0 + j];
            sP[c][j] = pk(v, v);
        }
        __syncthreads();
        const float* wp = W1 + (size_t)h0 * KD + d;
#pragma unroll 1
        for (int j = 0; j < HCHUNK; j += 8) {
            u64 w[8];
#pragma unroll
            for (int u = 0; u < 8; u++)
                w[u] = *reinterpret_cast<const u64*>(wp + (size_t)(j + u) * KD);
#pragma unroll
            for (int u = 0; u < 8; u++) {
#pragma unroll
                for (int c = 0; c < NOUT; c++)
                    acc[c] = ffma2(sP[c][j + u], w[u], acc[c]);
            }
        }
    }
    float* op = g_part + (size_t)blockIdx.y * NOUT * KD + d;
#pragma unroll
    for (int c = 0; c < NOUT; c++)
        *reinterpret_cast<u64*>(op + (size_t)c * KD) = acc[c];
}

// ---------------- reduce partials -> M ----------------
__global__ void k_reduce() {
    int i = blockIdx.x * 256 + threadIdx.x;   // < NOUT*KD = 627200
    float s = 0.f;
#pragma unroll
    for (int p = 0; p < HSPLIT; p++) s += g_part[(size_t)p * (NOUT * KD) + i];
    g_M[i] = s;
}

// ---------------- k2: logits = feats @ M^T + bias_f, then softmax/argmax/box decode ----------------
// 256 threads = 8 warps, one warp per ROI row. M tiled through shared (L2-resident source).
__global__ __launch_bounds__(256) void k2_head(const float* __restrict__ feats,
                                               const float* __restrict__ props) {
    __shared__ u64 sM[NOUT][DCHUNK / 2];
    int tid = threadIdx.x;
    int warp = tid >> 5, lane = tid & 31;
    int row = blockIdx.x * 8 + warp;
    const float* fr = feats + (size_t)row * KD;

    u64 acc[NOUT];
#pragma unroll
    for (int c = 0; c < NOUT; c++) acc[c] = 0ull;

    for (int chunk = 0; chunk < KD / DCHUNK; chunk++) {   // 98 chunks
        int d0 = chunk * DCHUNK;
        __syncthreads();
        for (int idx = tid; idx < NOUT * (DCHUNK / 2); idx += 256) {
            int c = idx / (DCHUNK / 2), p = idx % (DCHUNK / 2);
            sM[c][p] = *reinterpret_cast<const u64*>(&g_M[(size_t)c * KD + d0 + 2 * p]);
        }
        __syncthreads();
#pragma unroll
        for (int it = 0; it < (DCHUNK / 2) / 32; it++) {  // 4 iterations
            int p = it * 32 + lane;
            u64 f = *reinterpret_cast<const u64*>(fr + d0 + 2 * p);
#pragma unroll
            for (int c = 0; c < NOUT; c++)
                acc[c] = ffma2(f, sM[c][p], acc[c]);
        }
    }

    // reduce within warp
    float tot[NOUT];
#pragma unroll
    for (int c = 0; c < NOUT; c++) {
        float2 v = unpk(acc[c]);
        float s = v.x + v.y;
#pragma unroll
        for (int o = 16; o > 0; o >>= 1) s += __shfl_down_sync(0xffffffffu, s, o);
        tot[c] = s;   // valid on lane 0
    }

    if (lane == 0) {
#pragma unroll
        for (int c = 0; c < NOUT; c++) tot[c] += g_biasf[c];
        // softmax-max over 21 classes; score = max prob = 1/sum(exp(l - lmax))
        float m = tot[0]; int idx = 0;
#pragma unroll
        for (int c = 1; c < NCLS_; c++) { if (tot[c] > m) { m = tot[c]; idx = c; } }
        float ssum = 0.f;
#pragma unroll
        for (int c = 0; c < NCLS_; c++) ssum += expf(tot[c] - m);
        float score = 1.f / ssum;
        bool valid = (idx != 0) && (score >= 0.01f);
        float p0 = props[row * 4 + 0], p1 = props[row * 4 + 1];
        float p2 = props[row * 4 + 2], p3 = props[row * 4 + 3];
        float px = p0 + p2 * tot[NCLS_ + 0];
        float py = p1 + p3 * tot[NCLS_ + 1];
        float pw = p2 * expf(tot[NCLS_ + 2]);
        float ph = p3 * expf(tot[NCLS_ + 3]);
        g_score[row] = valid ? score : 0.f;
        g_boxes[row * 4 + 0] = px;
        g_boxes[row * 4 + 1] = py;
        g_boxes[row * 4 + 2] = pw;
        g_boxes[row * 4 + 3] = ph;
    }
}

// ---------------- k3: exact greedy NMS per batch + final outputs ----------------
__global__ __launch_bounds__(512) void k3_nms(float* __restrict__ out) {
    __shared__ float sraw[512];
    __shared__ float ss[512], sx0[512], sy0[512], sx1[512], sy1[512], sa[512];
    __shared__ short sord[512];
    __shared__ unsigned char ssup[512];

    int b = blockIdx.x, t = threadIdx.x;
    int gi = b * 512 + t;
    float sc = g_score[gi];
    sraw[t] = sc;
    float bx = g_boxes[gi * 4 + 0], by = g_boxes[gi * 4 + 1];
    float bw = g_boxes[gi * 4 + 2], bh = g_boxes[gi * 4 + 3];
    __syncthreads();

    // stable descending rank (matches jnp.argsort(-scores), stable)
    int r = 0;
    for (int i = 0; i < 512; i++) {
        float si = sraw[i];
        r += (si > sc) || (si == sc && i < t);
    }

    // clipped coords for IoU (reference clips inside NMS only)
    float x0 = fminf(fmaxf(bx, 0.f), 599.f);
    float y0 = fminf(fmaxf(by, 0.f), 599.f);
    float x1 = fminf(fmaxf(bx + bw - 1.f, 0.f), 599.f);
    float y1 = fminf(fmaxf(by + bh - 1.f, 0.f), 599.f);
    float area = fmaxf(x1 - x0 + 1.f, 0.f) * fmaxf(y1 - y0 + 1.f, 0.f);

    ss[r] = sc; sx0[r] = x0; sy0[r] = y0; sx1[r] = x1; sy1[r] = y1; sa[r] = area;
    sord[r] = (short)t;
    ssup[t] = 0;
    __syncthreads();

    // serial greedy suppression, exact replica of the fori_loop semantics
    for (int i = 0; i < 512; i++) {
        bool alive = (!ssup[i]) && (ss[i] > 0.f);
        if (alive && t != i) {
            float ix0 = fmaxf(sx0[i], sx0[t]);
            float iy0 = fmaxf(sy0[i], sy0[t]);
            float ix1 = fminf(sx1[i], sx1[t]);
            float iy1 = fminf(sy1[i], sy1[t]);
            float inter = fmaxf(ix1 - ix0 + 1.f, 0.f) * fmaxf(iy1 - iy0 + 1.f, 0.f);
            float iou = inter / (sa[i] + sa[t] - inter + 1e-9f);
            if (iou > 0.5f) ssup[t] = 1;
        }
        __syncthreads();
    }

    bool keep = (!ssup[t]) && (ss[t] > 0.f);
    int orig = sord[t];
    int go = b * 512 + orig;

    out[go] = keep ? ss[t] : 0.f;   // clss_out [B,N]

    float obx = g_boxes[go * 4 + 0], oby = g_boxes[go * 4 + 1];
    float obw = g_boxes[go * 4 + 2], obh = g_boxes[go * 4 + 3];
    float* ob = out + NROI + (size_t)go * 4;  // bboxes_out [B,N,4] after clss_out
    if (keep) {
        ob[0] = obx; ob[1] = oby;
        ob[2] = obx + obw - 1.f;
        ob[3] = oby + obh - 1.f;
    } else {
        // where(keep, boxes, 0) then x1 = x0 + w - 1  ->  (0,0,-1,-1)
        ob[0] = 0.f; ob[1] = 0.f; ob[2] = -1.f; ob[3] = -1.f;
    }
}

extern "C" void kernel_launch(void* const* d_in, const int* in_sizes, int n_in,
                              void* d_out, int out_size) {
    (void)in_sizes; (void)n_in; (void)out_size;
    const float* rois  = (const float*)d_in[0];   // [4,512,512,7,7] -> feats [2048,25088]
    const float* props = (const float*)d_in[1];   // [4,512,4]
    const float* W1    = (const float*)d_in[2];   // [4096,25088]
    const float* b1    = (const float*)d_in[3];   // [4096]
    const float* Wc    = (const float*)d_in[4];   // [21,4096]
    const float* bc    = (const float*)d_in[5];   // [21]
    const float* Wr    = (const float*)d_in[6];   // [4,4096]
    const float* br    = (const float*)d_in[7];   // [4]
    float* out = (float*)d_out;                   // [2048] clss + [2048*4] bboxes

    k_bias<<<NOUT, 256>>>(b1, Wc, bc, Wr, br);
    dim3 g1(KD / 512, HSPLIT);                    // (49, 16)
    k1_partial<<<g1, 256>>>(W1, Wc, Wr);
    k_reduce<<<(NOUT * KD) / 256, 256>>>();       // 2450 blocks
    k2_head<<<NROI / 8, 256>>>(rois, props);      // 256 blocks
    k3_nms<<<4, 512>>>(out);
}

// round 2
// speedup vs baseline: 1.3240x; 1.3240x over previous
#include <cuda_runtime.h>
#include <cstdint>

typedef unsigned long long u64;

// ---- packed f32x2 helpers (B300: FFMA2 doubles fp32 rate, PTX-only) ----
__device__ __forceinline__ u64 ffma2(u64 a, u64 b, u64 c) {
    u64 d;
    asm("fma.rn.f32x2 %0, %1, %2, %3;" : "=l"(d) : "l"(a), "l"(b), "l"(c));
    return d;
}
__device__ __forceinline__ u64 addf2(u64 a, u64 b) {
    u64 d;
    asm("add.rn.f32x2 %0, %1, %2;" : "=l"(d) : "l"(a), "l"(b));
    return d;
}
__device__ __forceinline__ u64 pk(float x, float y) {
    u64 r; asm("mov.b64 %0, {%1, %2};" : "=l"(r) : "f"(x), "f"(y)); return r;
}
__device__ __forceinline__ float2 unpk(u64 v) {
    float2 r;
    asm("mov.b64 {%0, %1}, %2;" : "=f"(r.x), "=f"(r.y) : "l"(v));
    return r;
}

#define KD 25088      // D = 512*7*7
#define KH 4096       // hidden
#define NROI 2048     // B*N
#define NOUT 25       // 21 cls + 4 reg
#define NCLS_ 21
#define HSPLIT 16
#define HPER (KH / HSPLIT)    // 256
#define KSEG 512              // k2 k-segment per block
#define NSEG (KD / KSEG)      // 49
#define KC 64                 // k2 chunk

// scratch (static device arrays: no allocations allowed)
__device__ __align__(16) float g_part[(size_t)HSPLIT * NOUT * KD]; // 40.1 MB
__device__ __align__(16) float g_M[NOUT * KD];                     // 2.5 MB
__device__ __align__(16) u64 g_p2[(size_t)NSEG * 16 * NOUT * 64];  // 10 MB
__device__ float g_biasf[NOUT];
__device__ float g_score[NROI];
__device__ __align__(16) float g_boxes[NROI * 4];

// ---------------- fused bias: bias_f[c] = sum_h b1[h]*P[c,h] + (bc|br)[c] ----------------
__global__ void k_bias(const float* __restrict__ b1, const float* __restrict__ Wc,
                       const float* __restrict__ bc, const float* __restrict__ Wr,
                       const float* __restrict__ br) {
    int c = blockIdx.x;
    int tid = threadIdx.x;
    const float* p = (c < NCLS_) ? (Wc + (size_t)c * KH) : (Wr + (size_t)(c - NCLS_) * KH);
    float s = 0.f;
    for (int h = tid; h < KH; h += 256) s += b1[h] * p[h];
    __shared__ float red[256];
    red[tid] = s;
    __syncthreads();
    for (int o = 128; o > 0; o >>= 1) {
        if (tid < o) red[tid] += red[tid + o];
        __syncthreads();
    }
    if (tid == 0) g_biasf[c] = red[0] + ((c < NCLS_) ? bc[c] : br[c - NCLS_]);
}

// ---------------- k1: partial M[c,d] = sum_{h in range} P[c,h] * W1[h,d] ----------------
// Block 128 thr. Thread owns 4 consecutive d (2 f32x2 pairs, LDG.128 per h-row).
// P duplicated in shared as 16B pairs {(v0,v0),(v1,v1)} -> 1 broadcast LDS.128 per 2 h.
__global__ __launch_bounds__(128, 3) void k1_partial(const float* __restrict__ W1,
                                                     const float* __restrict__ Wc,
                                                     const float* __restrict__ Wr) {
    __shared__ __align__(16) u64 sPd[64][NOUT][2];   // 25.6 KB
    int tid = threadIdx.x;
    int d = blockIdx.x * 512 + tid * 4;
    int hbase = blockIdx.y * HPER;

    u64 acc[NOUT][2];
#pragma unroll
    for (int c = 0; c < NOUT; c++) { acc[c][0] = 0ull; acc[c][1] = 0ull; }

    for (int ch = 0; ch < HPER / 128; ch++) {      // 2 chunks of 128 h
        int h0 = hbase + ch * 128;
        __syncthreads();
        for (int i = tid; i < 64 * NOUT; i += 128) {
            int c = i / 64, j2 = i % 64;
            int h = h0 + 2 * j2;
            float v0, v1;
            if (c < NCLS_) { v0 = Wc[(size_t)c * KH + h]; v1 = Wc[(size_t)c * KH + h + 1]; }
            else { v0 = Wr[(size_t)(c - NCLS_) * KH + h]; v1 = Wr[(size_t)(c - NCLS_) * KH + h + 1]; }
            sPd[j2][c][0] = pk(v0, v0);
            sPd[j2][c][1] = pk(v1, v1);
        }
        __syncthreads();
        for (int jb = 0; jb < 64; jb += 2) {       // batch 2 j2 = 4 h-rows
            u64 wv[8];
#pragma unroll
            for (int q = 0; q < 4; q++) {          // h = h0 + 2*jb + q
                const float* wp = W1 + (size_t)(h0 + 2 * jb + q) * KD + d;
                wv[2 * q]     = *reinterpret_cast<const u64*>(wp);
                wv[2 * q + 1] = *reinterpret_cast<const u64*>(wp + 2);
            }
#pragma unroll
            for (int u = 0; u < 2; u++) {          // j2 = jb + u
#pragma unroll
                for (int c = 0; c < NOUT; c++) {
                    u64 m0 = sPd[jb + u][c][0];    // (P[h],P[h]) broadcast
                    u64 m1 = sPd[jb + u][c][1];    // (P[h+1],P[h+1])
                    acc[c][0] = ffma2(m0, wv[4 * u + 0], acc[c][0]);
                    acc[c][1] = ffma2(m0, wv[4 * u + 1], acc[c][1]);
                    acc[c][0] = ffma2(m1, wv[4 * u + 2], acc[c][0]);
                    acc[c][1] = ffma2(m1, wv[4 * u + 3], acc[c][1]);
                }
            }
        }
    }
    float* op = g_part + (size_t)blockIdx.y * NOUT * KD + d;
#pragma unroll
    for (int c = 0; c < NOUT; c++) {
        u64* o = reinterpret_cast<u64*>(op + (size_t)c * KD);
        o[0] = acc[c][0]; o[1] = acc[c][1];
    }
}

// ---------------- reduce partials -> M (u64 vectorized) ----------------
__global__ void k_reduce() {
    int i = blockIdx.x * 256 + threadIdx.x;   // < 313600 u64
    const u64* gp = reinterpret_cast<const u64*>(g_part);
    u64 s = gp[i];
#pragma unroll
    for (int p = 1; p < HSPLIT; p++) s = addf2(s, gp[(size_t)p * 313600 + i]);
    reinterpret_cast<u64*>(g_M)[i] = s;
}

// ---------------- k2_main: partial logits via register-tiled GEMM ----------------
// grid (16 rowgroups, 49 ksegs), block 128 (4 warps; warp w owns k-quarter).
// Row-pair packing: sF[p][k] = (feats[2p][k], feats[2p+1][k]).
// Lane owns pairs {lane, lane+32}; acc[25][2] u64 = 100 regs.
__global__ __launch_bounds__(128, 3) void k2_main(const float* __restrict__ feats) {
    __shared__ u64 sF[64][65];                       // 33.3 KB, [pair][k] pitch 65
    __shared__ __align__(16) u64 sMd[32][NOUT][2];   // 12.8 KB, dup M pairs
    int tid = threadIdx.x, w = tid >> 5, lane = tid & 31;
    int rg = blockIdx.x, ks = blockIdx.y;
    int k_base = ks * KSEG;

    u64 acc[NOUT][2];
#pragma unroll
    for (int c = 0; c < NOUT; c++) { acc[c][0] = 0ull; acc[c][1] = 0ull; }

    for (int ch = 0; ch < KSEG / KC; ch++) {         // 8 chunks
        int k0 = k_base + ch * KC;
        __syncthreads();
        // stage duplicated M: 32 k2 x 25 c entries
        for (int i = tid; i < 32 * NOUT; i += 128) {
            int c = i >> 5, k2 = i & 31;
            const float* mp = g_M + (size_t)c * KD + k0 + 2 * k2;
            sMd[k2][c][0] = pk(mp[0], mp[0]);
            sMd[k2][c][1] = pk(mp[1], mp[1]);
        }
        // stage feats row-pairs: warp w stages pairs [w*16, w*16+16), batched 8 (MLP)
        for (int pb = w * 16; pb < w * 16 + 16; pb += 8) {
            u64 va[8], vb[8];
#pragma unroll
            for (int q = 0; q < 8; q++) {
                int r0 = (rg * 64 + pb + q) << 1;
                va[q] = *reinterpret_cast<const u64*>(feats + (size_t)r0 * KD + k0 + 2 * lane);
                vb[q] = *reinterpret_cast<const u64*>(feats + (size_t)(r0 + 1) * KD + k0 + 2 * lane);
            }
#pragma unroll
            for (int q = 0; q < 8; q++) {
                float2 fa = unpk(va[q]), fb = unpk(vb[q]);
                sF[pb + q][2 * lane]     = pk(fa.x, fb.x);
                sF[pb + q][2 * lane + 1] = pk(fa.y, fb.y);
            }
        }
        __syncthreads();
        // compute: warp's 16-k quarter, 2 k per step
        for (int kk = 0; kk < 16; kk += 2) {
            int k = w * 16 + kk;
            int k2 = k >> 1;
            u64 f0a = sF[lane][k],      f0b = sF[lane][k + 1];
            u64 f1a = sF[lane + 32][k], f1b = sF[lane + 32][k + 1];
#pragma unroll
            for (int c = 0; c < NOUT; c++) {
                u64 m0 = sMd[k2][c][0];   // broadcast (LDS.128 pair)
                u64 m1 = sMd[k2][c][1];
                acc[c][0] = ffma2(f0a, m0, acc[c][0]);
                acc[c][0] = ffma2(f0b, m1, acc[c][0]);
                acc[c][1] = ffma2(f1a, m0, acc[c][1]);
                acc[c][1] = ffma2(f1b, m1, acc[c][1]);
            }
        }
    }

    // cross-warp k-reduction in shared (reuse sF area), then write block partial
    __syncthreads();
    u64* sred = &sF[0][0];
    u64* sR0 = sred;           // 1600 u64
    u64* sR1 = sred + 1600;
    if (w == 0) {
#pragma unroll
        for (int c = 0; c < NOUT; c++) { sR0[c * 64 + lane] = acc[c][0]; sR0[c * 64 + 32 + lane] = acc[c][1]; }
    } else if (w == 2) {
#pragma unroll
        for (int c = 0; c < NOUT; c++) { sR1[c * 64 + lane] = acc[c][0]; sR1[c * 64 + 32 + lane] = acc[c][1]; }
    }
    __syncthreads();
    if (w == 1) {
#pragma unroll
        for (int c = 0; c < NOUT; c++) {
            sR0[c * 64 + lane]      = addf2(sR0[c * 64 + lane], acc[c][0]);
            sR0[c * 64 + 32 + lane] = addf2(sR0[c * 64 + 32 + lane], acc[c][1]);
        }
    } else if (w == 3) {
#pragma unroll
        for (int c = 0; c < NOUT; c++) {
            sR1[c * 64 + lane]      = addf2(sR1[c * 64 + lane], acc[c][0]);
            sR1[c * 64 + 32 + lane] = addf2(sR1[c * 64 + 32 + lane], acc[c][1]);
        }
    }
    __syncthreads();
    u64* outp = g_p2 + (size_t)(ks * 16 + rg) * (NOUT * 64);
    for (int i = tid; i < NOUT * 64; i += 128)
        outp[i] = addf2(sR0[i], sR1[i]);
}

// ---------------- k2r: sum 49 seg partials per row + softmax/argmax/box decode ----------------
// warp per row; lane l covers segments {l, l+32}.
__global__ __launch_bounds__(256) void k2r(const float* __restrict__ props) {
    int tid = threadIdx.x, lane = tid & 31;
    int row = blockIdx.x * 8 + (tid >> 5);
    int rg = row >> 7, pp = (row >> 1) & 63, h = row & 1;
    const float* base = reinterpret_cast<const float*>(g_p2);

    float t[NOUT];
#pragma unroll
    for (int c = 0; c < NOUT; c++) t[c] = 0.f;
#pragma unroll
    for (int half = 0; half < 2; half++) {
        int s = lane + half * 32;
        if (s < NSEG) {
            size_t b = ((size_t)(s * 16 + rg) * NOUT) * 64;
#pragma unroll
            for (int c = 0; c < NOUT; c++)
                t[c] += base[(b + c * 64 + pp) * 2 + h];
        }
    }
#pragma unroll
    for (int c = 0; c < NOUT; c++) {
#pragma unroll
        for (int o = 16; o > 0; o >>= 1) t[c] += __shfl_xor_sync(0xffffffffu, t[c], o);
    }

    if (lane == 0) {
#pragma unroll
        for (int c = 0; c < NOUT; c++) t[c] += g_biasf[c];
        float m = t[0]; int idx = 0;
#pragma unroll
        for (int c = 1; c < NCLS_; c++) { if (t[c] > m) { m = t[c]; idx = c; } }
        float ssum = 0.f;
#pragma unroll
        for (int c = 0; c < NCLS_; c++) ssum += expf(t[c] - m);
        float score = 1.f / ssum;
        bool valid = (idx != 0) && (score >= 0.01f);
        float p0 = props[row * 4 + 0], p1 = props[row * 4 + 1];
        float p2 = props[row * 4 + 2], p3 = props[row * 4 + 3];
        g_score[row] = valid ? score : 0.f;
        g_boxes[row * 4 + 0] = p0 + p2 * t[NCLS_ + 0];
        g_boxes[row * 4 + 1] = p1 + p3 * t[NCLS_ + 1];
        g_boxes[row * 4 + 2] = p2 * expf(t[NCLS_ + 2]);
        g_boxes[row * 4 + 3] = p3 * expf(t[NCLS_ + 3]);
    }
}

// ---------------- k3: exact greedy NMS per batch + final outputs ----------------
__global__ __launch_bounds__(512) void k3_nms(float* __restrict__ out) {
    __shared__ float sraw[512];
    __shared__ float ss[512], sx0[512], sy0[512], sx1[512], sy1[512], sa[512];
    __shared__ short sord[512];
    __shared__ unsigned char ssup[512];

    int b = blockIdx.x, t = threadIdx.x;
    int gi = b * 512 + t;
    float sc = g_score[gi];
    sraw[t] = sc;
    float bx = g_boxes[gi * 4 + 0], by = g_boxes[gi * 4 + 1];
    float bw = g_boxes[gi * 4 + 2], bh = g_boxes[gi * 4 + 3];
    __syncthreads();

    int r = 0;
    for (int i = 0; i < 512; i++) {
        float si = sraw[i];
        r += (si > sc) || (si == sc && i < t);
    }

    float x0 = fminf(fmaxf(bx, 0.f), 599.f);
    float y0 = fminf(fmaxf(by, 0.f), 599.f);
    float x1 = fminf(fmaxf(bx + bw - 1.f, 0.f), 599.f);
    float y1 = fminf(fmaxf(by + bh - 1.f, 0.f), 599.f);
    float area = fmaxf(x1 - x0 + 1.f, 0.f) * fmaxf(y1 - y0 + 1.f, 0.f);

    ss[r] = sc; sx0[r] = x0; sy0[r] = y0; sx1[r] = x1; sy1[r] = y1; sa[r] = area;
    sord[r] = (short)t;
    ssup[t] = 0;
    __syncthreads();

    for (int i = 0; i < 512; i++) {
        bool alive = (!ssup[i]) && (ss[i] > 0.f);
        if (alive && t != i) {
            float ix0 = fmaxf(sx0[i], sx0[t]);
            float iy0 = fmaxf(sy0[i], sy0[t]);
            float ix1 = fminf(sx1[i], sx1[t]);
            float iy1 = fminf(sy1[i], sy1[t]);
            float inter = fmaxf(ix1 - ix0 + 1.f, 0.f) * fmaxf(iy1 - iy0 + 1.f, 0.f);
            float iou = inter / (sa[i] + sa[t] - inter + 1e-9f);
            if (iou > 0.5f) ssup[t] = 1;
        }
        __syncthreads();
    }

    bool keep = (!ssup[t]) && (ss[t] > 0.f);
    int orig = sord[t];
    int go = b * 512 + orig;

    out[go] = keep ? ss[t] : 0.f;

    float obx = g_boxes[go * 4 + 0], oby = g_boxes[go * 4 + 1];
    float obw = g_boxes[go * 4 + 2], obh = g_boxes[go * 4 + 3];
    float* ob = out + NROI + (size_t)go * 4;
    if (keep) {
        ob[0] = obx; ob[1] = oby;
        ob[2] = obx + obw - 1.f;
        ob[3] = oby + obh - 1.f;
    } else {
        ob[0] = 0.f; ob[1] = 0.f; ob[2] = -1.f; ob[3] = -1.f;
    }
}

extern "C" void kernel_launch(void* const* d_in, const int* in_sizes, int n_in,
                              void* d_out, int out_size) {
    (void)in_sizes; (void)n_in; (void)out_size;
    const float* rois  = (const float*)d_in[0];
    const float* props = (const float*)d_in[1];
    const float* W1    = (const float*)d_in[2];
    const float* b1    = (const float*)d_in[3];
    const float* Wc    = (const float*)d_in[4];
    const float* bc    = (const float*)d_in[5];
    const float* Wr    = (const float*)d_in[6];
    const float* br    = (const float*)d_in[7];
    float* out = (float*)d_out;

    k_bias<<<NOUT, 256>>>(b1, Wc, bc, Wr, br);
    dim3 g1(KD / 512, HSPLIT);                 // (49, 16)
    k1_partial<<<g1, 128>>>(W1, Wc, Wr);
    k_reduce<<<313600 / 256, 256>>>();         // 1225 blocks
    dim3 g2(16, NSEG);                         // (16, 49)
    k2_main<<<g2, 128>>>(rois);
    k2r<<<NROI / 8, 256>>>(props);
    k3_nms<<<4, 512>>>(out);
}

// round 3
// speedup vs baseline: 1.3512x; 1.0205x over previous
#include <cuda_runtime.h>
#include <cstdint>

typedef unsigned long long u64;

// ---- packed f32x2 helpers (B300 FFMA2: 2 fp32 MACs per instruction) ----
__device__ __forceinline__ u64 ffma2(u64 a, u64 b, u64 c) {
    u64 d;
    asm("fma.rn.f32x2 %0, %1, %2, %3;" : "=l"(d) : "l"(a), "l"(b), "l"(c));
    return d;
}
__device__ __forceinline__ u64 addf2(u64 a, u64 b) {
    u64 d;
    asm("add.rn.f32x2 %0, %1, %2;" : "=l"(d) : "l"(a), "l"(b));
    return d;
}
__device__ __forceinline__ u64 pk(float x, float y) {
    u64 r; asm("mov.b64 %0, {%1, %2};" : "=l"(r) : "f"(x), "f"(y)); return r;
}
__device__ __forceinline__ float2 unpk(u64 v) {
    float2 r;
    asm("mov.b64 {%0, %1}, %2;" : "=f"(r.x), "=f"(r.y) : "l"(v));
    return r;
}

#define KD 25088
#define KH 4096
#define NROI 2048
#define NOUT 25
#define NCLS_ 21
#define HSPLIT 16
#define HPER (KH / HSPLIT)    // 256
#define KSEG 512              // k2 k-segment per block
#define NSEG (KD / KSEG)      // 49
#define NRG 32                // k2 rowgroups (2048/64)
#define PIT 68                // k2 shared pitch (bank-friendly for strided LDS.128)

// scratch (static device arrays: no allocations allowed)
__device__ __align__(16) float g_part[(size_t)HSPLIT * NOUT * KD]; // 40.1 MB
__device__ __align__(16) float g_M[NOUT * KD];                     // 2.5 MB
__device__ __align__(16) float g_p2[(size_t)NSEG * NRG * NOUT * 64]; // 10 MB
__device__ float g_biasf[NOUT];
__device__ float g_score[NROI];
__device__ __align__(16) float g_boxes[NROI * 4];

// ---------------- fused bias: bias_f[c] = sum_h b1[h]*P[c,h] + (bc|br)[c] ----------------
__global__ void k_bias(const float* __restrict__ b1, const float* __restrict__ Wc,
                       const float* __restrict__ bc, const float* __restrict__ Wr,
                       const float* __restrict__ br) {
    int c = blockIdx.x;
    int tid = threadIdx.x;
    const float* p = (c < NCLS_) ? (Wc + (size_t)c * KH) : (Wr + (size_t)(c - NCLS_) * KH);
    float s = 0.f;
    for (int h = tid; h < KH; h += 256) s += b1[h] * p[h];
    __shared__ float red[256];
    red[tid] = s;
    __syncthreads();
    for (int o = 128; o > 0; o >>= 1) {
        if (tid < o) red[tid] += red[tid + o];
        __syncthreads();
    }
    if (tid == 0) g_biasf[c] = red[0] + ((c < NCLS_) ? bc[c] : br[c - NCLS_]);
}

// ---------------- k1: partial M[c,d] = sum_h P[c,h]*W1[h,d], software-pipelined ----------------
// Thread owns 4 consecutive d. P duplicated pairs in shared (1 broadcast LDS.128 per 2 h per c).
// W rows prefetched one iteration (4 h) ahead to hide DRAM latency.
struct W4 { ulonglong2 v[4]; };

__device__ __forceinline__ void k1_loadW(W4& w, const float* __restrict__ W1,
                                         int h0, int jb, int d) {
#pragma unroll
    for (int q = 0; q < 4; q++)
        w.v[q] = *reinterpret_cast<const ulonglong2*>(W1 + (size_t)(h0 + 2 * jb + q) * KD + d);
}

__global__ __launch_bounds__(128, 3) void k1_partial(const float* __restrict__ W1,
                                                     const float* __restrict__ Wc,
                                                     const float* __restrict__ Wr) {
    __shared__ __align__(16) u64 sPd[64][NOUT][2];   // 25.6 KB (128-h chunk, dup pairs)
    int tid = threadIdx.x;
    int d = blockIdx.x * 512 + tid * 4;
    int hbase = blockIdx.y * HPER;

    u64 acc[NOUT][2];
#pragma unroll
    for (int c = 0; c < NOUT; c++) { acc[c][0] = 0ull; acc[c][1] = 0ull; }

    for (int ch = 0; ch < HPER / 128; ch++) {        // 2 chunks of 128 h
        int h0 = hbase + ch * 128;
        __syncthreads();
        for (int i = tid; i < 64 * NOUT; i += 128) {
            int c = i / 64, j2 = i % 64;
            int h = h0 + 2 * j2;
            float v0, v1;
            if (c < NCLS_) { v0 = Wc[(size_t)c * KH + h]; v1 = Wc[(size_t)c * KH + h + 1]; }
            else { v0 = Wr[(size_t)(c - NCLS_) * KH + h]; v1 = Wr[(size_t)(c - NCLS_) * KH + h + 1]; }
            sPd[j2][c][0] = pk(v0, v0);
            sPd[j2][c][1] = pk(v1, v1);
        }
        __syncthreads();

        W4 wa, wb;
        k1_loadW(wa, W1, h0, 0, d);
        for (int jb = 0; jb < 64; jb += 4) {
            k1_loadW(wb, W1, h0, jb + 2, d);         // prefetch
#pragma unroll
            for (int u = 0; u < 2; u++) {
#pragma unroll
                for (int c = 0; c < NOUT; c++) {
                    u64 m0 = sPd[jb + u][c][0];
                    u64 m1 = sPd[jb + u][c][1];
                    acc[c][0] = ffma2(m0, wa.v[2 * u].x, acc[c][0]);
                    acc[c][1] = ffma2(m0, wa.v[2 * u].y, acc[c][1]);
                    acc[c][0] = ffma2(m1, wa.v[2 * u + 1].x, acc[c][0]);
                    acc[c][1] = ffma2(m1, wa.v[2 * u + 1].y, acc[c][1]);
                }
            }
            if (jb + 4 < 64) k1_loadW(wa, W1, h0, jb + 4, d);   // prefetch
#pragma unroll
            for (int u = 0; u < 2; u++) {
#pragma unroll
                for (int c = 0; c < NOUT; c++) {
                    u64 m0 = sPd[jb + 2 + u][c][0];
                    u64 m1 = sPd[jb + 2 + u][c][1];
                    acc[c][0] = ffma2(m0, wb.v[2 * u].x, acc[c][0]);
                    acc[c][1] = ffma2(m0, wb.v[2 * u].y, acc[c][1]);
                    acc[c][0] = ffma2(m1, wb.v[2 * u + 1].x, acc[c][0]);
                    acc[c][1] = ffma2(m1, wb.v[2 * u + 1].y, acc[c][1]);
                }
            }
        }
    }
    float* op = g_part + (size_t)blockIdx.y * NOUT * KD + d;
#pragma unroll
    for (int c = 0; c < NOUT; c++) {
        ulonglong2 v; v.x = acc[c][0]; v.y = acc[c][1];
        *reinterpret_cast<ulonglong2*>(op + (size_t)c * KD) = v;
    }
}

// ---------------- reduce partials -> M (u64 vectorized) ----------------
__global__ void k_reduce() {
    int i = blockIdx.x * 256 + threadIdx.x;   // < 313600 u64
    const u64* gp = reinterpret_cast<const u64*>(g_part);
    u64 s = gp[i];
#pragma unroll
    for (int p = 1; p < HSPLIT; p++) s = addf2(s, gp[(size_t)p * 313600 + i]);
    reinterpret_cast<u64*>(g_M)[i] = s;
}

// ---------------- k2_main: k-major register-tiled GEMM ----------------
// grid (NRG=32 rowgroups, NSEG=49 ksegs), 128 thr (4 warps, warp = k-quarter of chunk).
// acc[c] accumulates (k,k+1) packed pairs; M broadcast as raw LDS.128 (4 k / phase),
// feats staged raw (no transpose). Double-buffered shared + LDG prefetch.
__global__ __launch_bounds__(128, 3) void k2_main(const float* __restrict__ feats) {
    __shared__ __align__(16) float sF[2][64 * PIT];   // 2 x 17408 B
    __shared__ __align__(16) float sM[2][NOUT * PIT]; // 2 x 6800 B
    int tid = threadIdx.x, w = tid >> 5, lane = tid & 31;
    int rg = blockIdx.x, ks = blockIdx.y;
    int rowbase = rg * 64;
    int kbase = ks * KSEG;

    u64 acc[NOUT][2];
#pragma unroll
    for (int c = 0; c < NOUT; c++) { acc[c][0] = 0ull; acc[c][1] = 0ull; }

    int frow = tid >> 4;            // staging: 8 rows per thread (stride 8)
    int fkq = (tid & 15) * 4;

    float4 fb[8]; float4 mb[4];
    // prologue: load + store chunk 0
    {
        int k0 = kbase;
#pragma unroll
        for (int q = 0; q < 8; q++)
            fb[q] = *reinterpret_cast<const float4*>(feats + (size_t)(rowbase + frow + 8 * q) * KD + k0 + fkq);
#pragma unroll
        for (int q = 0; q < 4; q++) {
            int idx = tid + 128 * q;
            if (idx < NOUT * 16)
                mb[q] = *reinterpret_cast<const float4*>(g_M + (size_t)(idx >> 4) * KD + k0 + (idx & 15) * 4);
        }
#pragma unroll
        for (int q = 0; q < 8; q++)
            *reinterpret_cast<float4*>(&sF[0][(frow + 8 * q) * PIT + fkq]) = fb[q];
#pragma unroll
        for (int q = 0; q < 4; q++) {
            int idx = tid + 128 * q;
            if (idx < NOUT * 16)
                *reinterpret_cast<float4*>(&sM[0][(idx >> 4) * PIT + (idx & 15) * 4]) = mb[q];
        }
    }
    __syncthreads();

    for (int ch = 0; ch < 8; ch++) {
        int b = ch & 1;
        bool pf = (ch < 7);
        if (pf) {
            int k0 = kbase + (ch + 1) * 64;
#pragma unroll
            for (int q = 0; q < 8; q++)
                fb[q] = *reinterpret_cast<const float4*>(feats + (size_t)(rowbase + frow + 8 * q) * KD + k0 + fkq);
#pragma unroll
            for (int q = 0; q < 4; q++) {
                int idx = tid + 128 * q;
                if (idx < NOUT * 16)
                    mb[q] = *reinterpret_cast<const float4*>(g_M + (size_t)(idx >> 4) * KD + k0 + (idx & 15) * 4);
            }
        }
        // compute: warp's 16-k quarter, 4 k per step
        const float* F = sF[b];
        const float* M = sM[b];
#pragma unroll
        for (int kk = 0; kk < 16; kk += 4) {
            int k = w * 16 + kk;
            ulonglong2 f0 = *reinterpret_cast<const ulonglong2*>(F + lane * PIT + k);
            ulonglong2 f1 = *reinterpret_cast<const ulonglong2*>(F + (lane + 32) * PIT + k);
#pragma unroll
            for (int c = 0; c < NOUT; c++) {
                ulonglong2 m = *reinterpret_cast<const ulonglong2*>(M + c * PIT + k);
                acc[c][0] = ffma2(f0.x, m.x, acc[c][0]);
                acc[c][0] = ffma2(f0.y, m.y, acc[c][0]);
                acc[c][1] = ffma2(f1.x, m.x, acc[c][1]);
                acc[c][1] = ffma2(f1.y, m.y, acc[c][1]);
            }
        }
        if (pf) {
            int nb = 1 - b;
#pragma unroll
            for (int q = 0; q < 8; q++)
                *reinterpret_cast<float4*>(&sF[nb][(frow + 8 * q) * PIT + fkq]) = fb[q];
#pragma unroll
            for (int q = 0; q < 4; q++) {
                int idx = tid + 128 * q;
                if (idx < NOUT * 16)
                    *reinterpret_cast<float4*>(&sM[nb][(idx >> 4) * PIT + (idx & 15) * 4]) = mb[q];
            }
            __syncthreads();
        }
    }

    // cross-warp k-reduction (reuse shared), then write float block-partials
    __syncthreads();
    u64* sR0 = reinterpret_cast<u64*>(&sF[0][0]);        // 1600 u64
    u64* sR1 = sR0 + NOUT * 64;
    if (w == 0) {
#pragma unroll
        for (int c = 0; c < NOUT; c++) { sR0[c * 64 + lane] = acc[c][0]; sR0[c * 64 + 32 + lane] = acc[c][1]; }
    } else if (w == 2) {
#pragma unroll
        for (int c = 0; c < NOUT; c++) { sR1[c * 64 + lane] = acc[c][0]; sR1[c * 64 + 32 + lane] = acc[c][1]; }
    }
    __syncthreads();
    if (w == 1) {
#pragma unroll
        for (int c = 0; c < NOUT; c++) {
            sR0[c * 64 + lane]      = addf2(sR0[c * 64 + lane], acc[c][0]);
            sR0[c * 64 + 32 + lane] = addf2(sR0[c * 64 + 32 + lane], acc[c][1]);
        }
    } else if (w == 3) {
#pragma unroll
        for (int c = 0; c < NOUT; c++) {
            sR1[c * 64 + lane]      = addf2(sR1[c * 64 + lane], acc[c][0]);
            sR1[c * 64 + 32 + lane] = addf2(sR1[c * 64 + 32 + lane], acc[c][1]);
        }
    }
    __syncthreads();
    float* outp = g_p2 + (size_t)(ks * NRG + rg) * (NOUT * 64);
    for (int i = tid; i < NOUT * 64; i += 128) {
        float2 v = unpk(addf2(sR0[i], sR1[i]));
        outp[i] = v.x + v.y;
    }
}

// ---------------- k2r: sum 49 seg partials per row + softmax/argmax/box decode ----------------
__global__ __launch_bounds__(256) void k2r(const float* __restrict__ props) {
    int tid = threadIdx.x, lane = tid & 31;
    int row = blockIdx.x * 8 + (tid >> 5);
    int rg = row >> 6, rowin = row & 63;

    float t[NOUT];
#pragma unroll
    for (int c = 0; c < NOUT; c++) t[c] = 0.f;
#pragma unroll
    for (int half = 0; half < 2; half++) {
        int s = lane + half * 32;
        if (s < NSEG) {
            const float* base = g_p2 + (size_t)(s * NRG + rg) * (NOUT * 64) + rowin;
#pragma unroll
            for (int c = 0; c < NOUT; c++) t[c] += base[c * 64];
        }
    }
#pragma unroll
    for (int c = 0; c < NOUT; c++) {
#pragma unroll
        for (int o = 16; o > 0; o >>= 1) t[c] += __shfl_xor_sync(0xffffffffu, t[c], o);
    }

    if (lane == 0) {
#pragma unroll
        for (int c = 0; c < NOUT; c++) t[c] += g_biasf[c];
        float m = t[0]; int idx = 0;
#pragma unroll
        for (int c = 1; c < NCLS_; c++) { if (t[c] > m) { m = t[c]; idx = c; } }
        float ssum = 0.f;
#pragma unroll
        for (int c = 0; c < NCLS_; c++) ssum += expf(t[c] - m);
        float score = 1.f / ssum;
        bool valid = (idx != 0) && (score >= 0.01f);
        float p0 = props[row * 4 + 0], p1 = props[row * 4 + 1];
        float p2 = props[row * 4 + 2], p3 = props[row * 4 + 3];
        g_score[row] = valid ? score : 0.f;
        g_boxes[row * 4 + 0] = p0 + p2 * t[NCLS_ + 0];
        g_boxes[row * 4 + 1] = p1 + p3 * t[NCLS_ + 1];
        g_boxes[row * 4 + 2] = p2 * expf(t[NCLS_ + 2]);
        g_boxes[row * 4 + 3] = p3 * expf(t[NCLS_ + 3]);
    }
}

// ---------------- k3: exact greedy NMS per batch + final outputs ----------------
__global__ __launch_bounds__(512) void k3_nms(float* __restrict__ out) {
    __shared__ float sraw[512];
    __shared__ float ss[512], sx0[512], sy0[512], sx1[512], sy1[512], sa[512];
    __shared__ short sord[512];
    __shared__ unsigned char ssup[512];

    int b = blockIdx.x, t = threadIdx.x;
    int gi = b * 512 + t;
    float sc = g_score[gi];
    sraw[t] = sc;
    float bx = g_boxes[gi * 4 + 0], by = g_boxes[gi * 4 + 1];
    float bw = g_boxes[gi * 4 + 2], bh = g_boxes[gi * 4 + 3];
    __syncthreads();

    int r = 0;
    for (int i = 0; i < 512; i++) {
        float si = sraw[i];
        r += (si > sc) || (si == sc && i < t);
    }

    float x0 = fminf(fmaxf(bx, 0.f), 599.f);
    float y0 = fminf(fmaxf(by, 0.f), 599.f);
    float x1 = fminf(fmaxf(bx + bw - 1.f, 0.f), 599.f);
    float y1 = fminf(fmaxf(by + bh - 1.f, 0.f), 599.f);
    float area = fmaxf(x1 - x0 + 1.f, 0.f) * fmaxf(y1 - y0 + 1.f, 0.f);

    ss[r] = sc; sx0[r] = x0; sy0[r] = y0; sx1[r] = x1; sy1[r] = y1; sa[r] = area;
    sord[r] = (short)t;
    ssup[t] = 0;
    __syncthreads();

    for (int i = 0; i < 512; i++) {
        bool alive = (!ssup[i]) && (ss[i] > 0.f);
        if (alive && t != i) {
            float ix0 = fmaxf(sx0[i], sx0[t]);
            float iy0 = fmaxf(sy0[i], sy0[t]);
            float ix1 = fminf(sx1[i], sx1[t]);
            float iy1 = fminf(sy1[i], sy1[t]);
            float inter = fmaxf(ix1 - ix0 + 1.f, 0.f) * fmaxf(iy1 - iy0 + 1.f, 0.f);
            float iou = inter / (sa[i] + sa[t] - inter + 1e-9f);
            if (iou > 0.5f) ssup[t] = 1;
        }
        __syncthreads();
    }

    bool keep = (!ssup[t]) && (ss[t] > 0.f);
    int orig = sord[t];
    int go = b * 512 + orig;

    out[go] = keep ? ss[t] : 0.f;

    float obx = g_boxes[go * 4 + 0], oby = g_boxes[go * 4 + 1];
    float obw = g_boxes[go * 4 + 2], obh = g_boxes[go * 4 + 3];
    float* ob = out + NROI + (size_t)go * 4;
    if (keep) {
        ob[0] = obx; ob[1] = oby;
        ob[2] = obx + obw - 1.f;
        ob[3] = oby + obh - 1.f;
    } else {
        ob[0] = 0.f; ob[1] = 0.f; ob[2] = -1.f; ob[3] = -1.f;
    }
}

extern "C" void kernel_launch(void* const* d_in, const int* in_sizes, int n_in,
                              void* d_out, int out_size) {
    (void)in_sizes; (void)n_in; (void)out_size;
    const float* rois  = (const float*)d_in[0];
    const float* props = (const float*)d_in[1];
    const float* W1    = (const float*)d_in[2];
    const float* b1    = (const float*)d_in[3];
    const float* Wc    = (const float*)d_in[4];
    const float* bc    = (const float*)d_in[5];
    const float* Wr    = (const float*)d_in[6];
    const float* br    = (const float*)d_in[7];
    float* out = (float*)d_out;

    k_bias<<<NOUT, 256>>>(b1, Wc, bc, Wr, br);
    dim3 g1(KD / 512, HSPLIT);                 // (49, 16)
    k1_partial<<<g1, 128>>>(W1, Wc, Wr);
    k_reduce<<<313600 / 256, 256>>>();
    dim3 g2(NRG, NSEG);                        // (32, 49)
    k2_main<<<g2, 128>>>(rois);
    k2r<<<NROI / 8, 256>>>(props);
    k3_nms<<<4, 512>>>(out);
}